// round 6
// baseline (speedup 1.0000x reference)
#include <cuda_runtime.h>
#include <cuda_bf16.h>
#include <math.h>
#include <stdint.h>

#define B_SZ     128
#define L_Q      64
#define L_D      512
#define E_DIM    300
#define N_K      11
#define NT       128        // docs per CTA chunk
#define NCHUNKS  4
#define NTHREADS 256
#define NKS      19         // 19*16 = 304 >= 300 k-steps

__device__ float g_pool[B_SZ * NCHUNKS * L_Q * N_K];
__device__ unsigned int g_cnt[B_SZ];   // zero-init; last CTA resets (graph-replay safe)

__device__ __forceinline__ void mma16816(float* c, const uint32_t* a, uint32_t b0, uint32_t b1) {
    asm volatile("mma.sync.aligned.m16n8k16.row.col.f32.bf16.bf16.f32 "
        "{%0,%1,%2,%3},{%4,%5,%6,%7},{%8,%9},{%0,%1,%2,%3};"
        : "+f"(c[0]), "+f"(c[1]), "+f"(c[2]), "+f"(c[3])
        : "r"(a[0]), "r"(a[1]), "r"(a[2]), "r"(a[3]), "r"(b0), "r"(b1));
}
// pack (x0 -> low16, x1 -> high16) as bf16x2 hi, and residual lo (in-register split)
__device__ __forceinline__ void cvt_pair(float x0, float x1, uint32_t& hi, uint32_t& lo) {
    uint32_t h;
    asm("cvt.rn.bf16x2.f32 %0, %1, %2;" : "=r"(h) : "f"(x1), "f"(x0));
    const float h0 = __uint_as_float(h << 16);
    const float h1 = __uint_as_float(h & 0xFFFF0000u);
    uint32_t l;
    asm("cvt.rn.bf16x2.f32 %0, %1, %2;" : "=r"(l) : "f"(x1 - h1), "f"(x0 - h0));
    hi = h; lo = l;
}
__device__ __forceinline__ float rcpa(float x) {
    float r; asm("rcp.approx.f32 %0,%1;" : "=f"(r) : "f"(x)); return r;
}
// 2^y for y in [-126, 15], pure fma/alu, err ~2e-6
__device__ __forceinline__ float exp2ff(float y) {
    float z = __fadd_rn(y, 12582912.0f);
    float f = __fadd_rn(y, -__fadd_rn(z, -12582912.0f));
    float p =              1.3333558e-3f;
    p = fmaf(p, f, 9.6181293e-3f);
    p = fmaf(p, f, 5.5504109e-2f);
    p = fmaf(p, f, 2.4022650e-1f);
    p = fmaf(p, f, 6.9314718e-1f);
    p = fmaf(p, f, 1.0f);
    int n = __float_as_int(z) - 0x4B400000;
    return p * __int_as_float((n + 127) << 23);
}

__global__ __launch_bounds__(NTHREADS, 2)
void knrm_hmma(const float* __restrict__ q,
               const float* __restrict__ d,
               const float* __restrict__ mq,
               const float* __restrict__ md,
               const float* __restrict__ w,
               const float* __restrict__ bias,
               float* __restrict__ out)
{
    __shared__ float s_invq[L_Q];
    __shared__ float s_invd[NT];
    __shared__ float s_maskd[NT];
    __shared__ float s_pool[L_Q * N_K];
    __shared__ float s_red[L_Q];
    __shared__ int   s_last;

    const int chunk = blockIdx.x;
    const int b     = blockIdx.y;
    const int n0g   = chunk * NT;
    const int tid   = threadIdx.x;
    const int lane  = tid & 31;
    const int warp  = tid >> 5;
    const int wm    = warp >> 2;     // 0..1 : query rows wm*32
    const int wn    = warp & 3;      // 0..3 : doc cols  wn*32
    const int qrow  = lane >> 2;     // fragment row/col-owner within 8
    const int cbase = (lane & 3) * 2;

    const float* __restrict__ qb = q + (size_t)b * L_Q * E_DIM;
    const float* __restrict__ db = d + (size_t)b * L_D * E_DIM;

    // ---- prologue: inverse L2 norms (warp per row); also warms L1/L2 ----
    for (int r = warp; r < L_Q; r += 8) {
        float ss = 0.f;
        for (int k = lane; k < E_DIM; k += 32) { float v = qb[r * E_DIM + k]; ss = fmaf(v, v, ss); }
        #pragma unroll
        for (int o = 16; o > 0; o >>= 1) ss += __shfl_xor_sync(0xffffffffu, ss, o);
        if (lane == 0) s_invq[r] = 1.0f / fmaxf(sqrtf(ss), 1e-12f);
    }
    for (int r = warp; r < NT; r += 8) {
        float ss = 0.f;
        const float* row = db + (size_t)(n0g + r) * E_DIM;
        for (int k = lane; k < E_DIM; k += 32) { float v = row[k]; ss = fmaf(v, v, ss); }
        #pragma unroll
        for (int o = 16; o > 0; o >>= 1) ss += __shfl_xor_sync(0xffffffffu, ss, o);
        if (lane == 0) s_invd[r] = 1.0f / fmaxf(sqrtf(ss), 1e-12f);
    }
    for (int i = tid; i < NT; i += NTHREADS) s_maskd[i] = md[b * L_D + n0g + i];
    for (int i = tid; i < L_Q * N_K; i += NTHREADS) s_pool[i] = 0.f;
    __syncthreads();

    // ---- hoist loop invariants: row pointers + inverse norms ----
    const float* qp[2][2];   // [mt][row-half]
    float iqa[2][2];
    #pragma unroll
    for (int mt = 0; mt < 2; ++mt)
        #pragma unroll
        for (int rh = 0; rh < 2; ++rh) {
            const int r = wm * 32 + mt * 16 + rh * 8 + qrow;
            qp[mt][rh]  = qb + (size_t)r * E_DIM + cbase;
            iqa[mt][rh] = s_invq[r];
        }
    const float* dp[4];
    float ivb[4];
    #pragma unroll
    for (int nt = 0; nt < 4; ++nt) {
        const int n = wn * 32 + nt * 8 + qrow;
        dp[nt]  = db + (size_t)(n0g + n) * E_DIM + cbase;
        ivb[nt] = s_invd[n];
    }

    // ---- GEMM: fragments loaded straight from global, bf16 hi/lo split in regs ----
    float acc[2][4][4];
    #pragma unroll
    for (int mt = 0; mt < 2; ++mt)
        #pragma unroll
        for (int nt = 0; nt < 4; ++nt)
            #pragma unroll
            for (int c = 0; c < 4; ++c) acc[mt][nt][c] = 0.f;

    #pragma unroll 1
    for (int ks = 0; ks < NKS; ++ks) {
        const int kb = ks * 16;
        const bool v1 = (kb + cbase + 8) < E_DIM;   // high-half pair validity (low always valid)

        uint32_t ah[2][4], al[2][4];
        #pragma unroll
        for (int mt = 0; mt < 2; ++mt) {
            const float iq0 = iqa[mt][0], iq1 = iqa[mt][1];
            const float2 f0 = *(const float2*)(qp[mt][0] + kb);
            const float2 f1 = *(const float2*)(qp[mt][1] + kb);
            const float2 f2 = v1 ? *(const float2*)(qp[mt][0] + kb + 8) : make_float2(0.f, 0.f);
            const float2 f3 = v1 ? *(const float2*)(qp[mt][1] + kb + 8) : make_float2(0.f, 0.f);
            cvt_pair(f0.x * iq0, f0.y * iq0, ah[mt][0], al[mt][0]);
            cvt_pair(f1.x * iq1, f1.y * iq1, ah[mt][1], al[mt][1]);
            cvt_pair(f2.x * iq0, f2.y * iq0, ah[mt][2], al[mt][2]);
            cvt_pair(f3.x * iq1, f3.y * iq1, ah[mt][3], al[mt][3]);
        }
        uint32_t bh[4][2], bl[4][2];
        #pragma unroll
        for (int nt = 0; nt < 4; ++nt) {
            const float iv = ivb[nt];
            const float2 g0 = *(const float2*)(dp[nt] + kb);
            const float2 g1 = v1 ? *(const float2*)(dp[nt] + kb + 8) : make_float2(0.f, 0.f);
            cvt_pair(g0.x * iv, g0.y * iv, bh[nt][0], bl[nt][0]);
            cvt_pair(g1.x * iv, g1.y * iv, bh[nt][1], bl[nt][1]);
        }
        #pragma unroll
        for (int mt = 0; mt < 2; ++mt)
            #pragma unroll
            for (int nt = 0; nt < 4; ++nt) {
                mma16816(acc[mt][nt], ah[mt], bh[nt][0], bh[nt][1]);  // hi*hi
                mma16816(acc[mt][nt], ah[mt], bl[nt][0], bl[nt][1]);  // hi*lo
                mma16816(acc[mt][nt], al[mt], bh[nt][0], bh[nt][1]);  // lo*hi
            }
    }

    // ---- pooling straight from accumulator fragments ----
    #pragma unroll
    for (int mt = 0; mt < 2; ++mt) {
        #pragma unroll
        for (int rh = 0; rh < 2; ++rh) {
            const int row = wm * 32 + mt * 16 + qrow + rh * 8;   // query index
            float pl[N_K];
            #pragma unroll
            for (int k = 0; k < N_K; ++k) pl[k] = 0.f;
            #pragma unroll
            for (int nt = 0; nt < 4; ++nt) {
                #pragma unroll
                for (int cm = 0; cm < 2; ++cm) {
                    const int nl = wn * 32 + nt * 8 + (lane & 3) * 2 + cm;  // local doc
                    const float s  = acc[mt][nt][rh * 2 + cm];
                    const float mv = s_maskd[nl];
                    const float base = exp2ff(fmaxf(s * s * -72.134752f, -126.f)); // e^{-50 s^2}
                    const float t    = exp2ff(s * 14.4269504f);                    // e^{10 s}
                    const float r    = rcpa(t);
                    const float t2 = t * t, r2 = r * r;
                    const float A1 = (base * t) * 0.60653066f;
                    const float A3 = (A1 * t2) * 0.018315639f;
                    const float A5 = (A3 * t2) * 3.3546263e-4f;
                    const float A7 = (A5 * t2) * 6.1442124e-6f;
                    const float A9 = (A7 * t2) * 1.1253517e-7f;
                    const float B1 = (base * r) * 0.60653066f;
                    const float B3 = (B1 * r2) * 0.018315639f;
                    const float B5 = (B3 * r2) * 3.3546263e-4f;
                    const float B7 = (B5 * r2) * 6.1442124e-6f;
                    const float B9 = (B7 * r2) * 1.1253517e-7f;
                    pl[1]  = fmaf(mv, A9, pl[1]);
                    pl[2]  = fmaf(mv, A7, pl[2]);
                    pl[3]  = fmaf(mv, A5, pl[3]);
                    pl[4]  = fmaf(mv, A3, pl[4]);
                    pl[5]  = fmaf(mv, A1, pl[5]);
                    pl[6]  = fmaf(mv, B1, pl[6]);
                    pl[7]  = fmaf(mv, B3, pl[7]);
                    pl[8]  = fmaf(mv, B5, pl[8]);
                    pl[9]  = fmaf(mv, B7, pl[9]);
                    pl[10] = fmaf(mv, B9, pl[10]);
                    const float d1 = s - 1.0f;   // kernel 0: sigma=1e-3
                    if (fabsf(d1) < 0.0125f) {
                        const float u = d1 * 849.321802f;
                        pl[0] = fmaf(mv, exp2ff(fmaxf(-u * u, -126.f)), pl[0]);
                    }
                }
            }
            #pragma unroll
            for (int k = 0; k < N_K; ++k) {
                float v = pl[k];
                v += __shfl_xor_sync(0xffffffffu, v, 1);
                v += __shfl_xor_sync(0xffffffffu, v, 2);
                if ((lane & 3) == 0) atomicAdd(&s_pool[row * N_K + k], v);
            }
        }
    }
    __syncthreads();

    // ---- publish chunk partials; last CTA of this batch finalizes ----
    float* gp = g_pool + (size_t)(b * NCHUNKS + chunk) * (L_Q * N_K);
    for (int i = tid; i < L_Q * N_K; i += NTHREADS) gp[i] = s_pool[i];
    __threadfence();
    __syncthreads();
    if (tid == 0) {
        unsigned int t = atomicAdd(&g_cnt[b], 1u);
        s_last = (t == NCHUNKS - 1);
    }
    __syncthreads();

    if (s_last) {
        __threadfence();
        const float* gb = g_pool + (size_t)b * NCHUNKS * L_Q * N_K;
        for (int i = tid; i < L_Q * N_K; i += NTHREADS)
            s_pool[i] = gb[i] + gb[L_Q * N_K + i] + gb[2 * L_Q * N_K + i] + gb[3 * L_Q * N_K + i];
        __syncthreads();
        if (tid < L_Q) {
            const float mqv = mq[b * L_Q + tid] * 0.01f;
            float cm = 0.f;
            #pragma unroll
            for (int k = 0; k < N_K; ++k)
                cm = fmaf(logf(fmaxf(s_pool[tid * N_K + k], 1e-10f)) * mqv, w[k], cm);
            s_red[tid] = cm;
        }
        __syncthreads();
        if (tid == 0) {
            float s = bias[0];
            #pragma unroll
            for (int m = 0; m < L_Q; ++m) s += s_red[m];
            out[b] = tanhf(s);
            g_cnt[b] = 0;   // reset for next graph replay
        }
    }
}

extern "C" void kernel_launch(void* const* d_in, const int* in_sizes, int n_in,
                              void* d_out, int out_size) {
    const float* q    = (const float*)d_in[0];   // [B, Lq, E]
    const float* d    = (const float*)d_in[1];   // [B, Ld, E]
    const float* mq   = (const float*)d_in[2];   // [B, Lq]
    const float* md   = (const float*)d_in[3];   // [B, Ld]
    const float* w    = (const float*)d_in[4];   // [1, K]
    const float* bias = (const float*)d_in[5];   // [1]
    float* out = (float*)d_out;                  // [B, 1]

    dim3 grid(NCHUNKS, B_SZ);
    knrm_hmma<<<grid, NTHREADS>>>(q, d, mq, md, w, bias, out);
}

// round 7
// speedup vs baseline: 1.2614x; 1.2614x over previous
#include <cuda_runtime.h>
#include <math.h>
#include <stdint.h>

#define B_SZ     128
#define L_Q      64
#define L_D      512
#define E_DIM    300
#define N_K      11
#define NT       128        // docs per CTA chunk
#define NCHUNKS  4
#define NTHREADS 256
#define KC       32         // k per pipeline chunk
#define NCK      10         // 10*32 = 320 >= 300 (zero-padded)
#define SW       36         // smem row stride (words): (4r+c)%32 distinct -> conflict-free

// dynamic smem (floats): buf0[6912] buf1[6912] invq[64] invd[128] maskd[128] pool[704] red[64]
#define BUF_W     6912      // A 64*36 + B 128*36
#define BOFF_B    2304      // B tile offset inside a buffer (words)
#define OFF_INVQ  (2 * BUF_W)
#define OFF_INVD  (OFF_INVQ + 64)
#define OFF_MASKD (OFF_INVD + 128)
#define OFF_POOL  (OFF_MASKD + 128)
#define OFF_RED   (OFF_POOL + 704)
#define SMEM_WORDS (OFF_RED + 64)
#define SMEM_BYTES (SMEM_WORDS * 4)

__device__ float g_pool[B_SZ * NCHUNKS * L_Q * N_K];
__device__ unsigned int g_cnt[B_SZ];   // zero-init; last CTA resets (graph-replay safe)

__device__ __forceinline__ void mma_tf32(float* c, const uint32_t* a, uint32_t b0, uint32_t b1) {
    asm volatile("mma.sync.aligned.m16n8k8.row.col.f32.tf32.tf32.f32 "
        "{%0,%1,%2,%3},{%4,%5,%6,%7},{%8,%9},{%0,%1,%2,%3};"
        : "+f"(c[0]), "+f"(c[1]), "+f"(c[2]), "+f"(c[3])
        : "r"(a[0]), "r"(a[1]), "r"(a[2]), "r"(a[3]), "r"(b0), "r"(b1));
}
__device__ __forceinline__ uint32_t cvt_tf32(float x) {
    uint32_t r; asm("cvt.rna.tf32.f32 %0, %1;" : "=r"(r) : "f"(x)); return r;
}
__device__ __forceinline__ float rcpa(float x) {
    float r; asm("rcp.approx.f32 %0,%1;" : "=f"(r) : "f"(x)); return r;
}
// 2^y for y in [-126, 15], pure fma/alu, err ~2e-6
__device__ __forceinline__ float exp2ff(float y) {
    float z = __fadd_rn(y, 12582912.0f);
    float f = __fadd_rn(y, -__fadd_rn(z, -12582912.0f));
    float p =              1.3333558e-3f;
    p = fmaf(p, f, 9.6181293e-3f);
    p = fmaf(p, f, 5.5504109e-2f);
    p = fmaf(p, f, 2.4022650e-1f);
    p = fmaf(p, f, 6.9314718e-1f);
    p = fmaf(p, f, 1.0f);
    int n = __float_as_int(z) - 0x4B400000;
    return p * __int_as_float((n + 127) << 23);
}

__global__ __launch_bounds__(NTHREADS, 2)
void knrm_tf32(const float* __restrict__ q,
               const float* __restrict__ d,
               const float* __restrict__ mq,
               const float* __restrict__ md,
               const float* __restrict__ w,
               const float* __restrict__ bias,
               float* __restrict__ out)
{
    extern __shared__ float smf[];
    __shared__ int s_last;

    float* s_invq  = smf + OFF_INVQ;
    float* s_invd  = smf + OFF_INVD;
    float* s_maskd = smf + OFF_MASKD;
    float* s_pool  = smf + OFF_POOL;
    float* s_red   = smf + OFF_RED;

    const int chunk = blockIdx.x;
    const int b     = blockIdx.y;
    const int n0g   = chunk * NT;
    const int tid   = threadIdx.x;
    const int lane  = tid & 31;
    const int warp  = tid >> 5;
    const int wm    = warp >> 2;     // 0..1 : query rows wm*32
    const int wn    = warp & 3;      // 0..3 : doc cols  wn*32
    const int qrow  = lane >> 2;
    const int c4    = lane & 3;

    const float* __restrict__ qb = q + (size_t)b * L_Q * E_DIM;
    const float* __restrict__ db = d + (size_t)b * L_D * E_DIM;

    // ---- prologue: inverse L2 norms, float4 (75 exact per row); warms L1 ----
    for (int r = warp; r < L_Q; r += 8) {
        float ss = 0.f;
        const float4* p = (const float4*)(qb + (size_t)r * E_DIM);
        for (int it = lane; it < 75; it += 32) {
            float4 v = p[it];
            ss = fmaf(v.x, v.x, fmaf(v.y, v.y, fmaf(v.z, v.z, fmaf(v.w, v.w, ss))));
        }
        #pragma unroll
        for (int o = 16; o > 0; o >>= 1) ss += __shfl_xor_sync(0xffffffffu, ss, o);
        if (lane == 0) s_invq[r] = 1.0f / fmaxf(sqrtf(ss), 1e-12f);
    }
    for (int r = warp; r < NT; r += 8) {
        float ss = 0.f;
        const float4* p = (const float4*)(db + (size_t)(n0g + r) * E_DIM);
        for (int it = lane; it < 75; it += 32) {
            float4 v = p[it];
            ss = fmaf(v.x, v.x, fmaf(v.y, v.y, fmaf(v.z, v.z, fmaf(v.w, v.w, ss))));
        }
        #pragma unroll
        for (int o = 16; o > 0; o >>= 1) ss += __shfl_xor_sync(0xffffffffu, ss, o);
        if (lane == 0) s_invd[r] = 1.0f / fmaxf(sqrtf(ss), 1e-12f);
    }
    for (int i = tid; i < NT; i += NTHREADS) s_maskd[i] = md[b * L_D + n0g + i];
    for (int i = tid; i < L_Q * N_K; i += NTHREADS) s_pool[i] = 0.f;
    __syncthreads();

    // ---- per-thread staging slots: 6 float4 per chunk ----
    const float* src[6];
    int   dst[6], kq[6];
    float inv[6];
    #pragma unroll
    for (int i = 0; i < 6; ++i) {
        const int idx = tid + i * NTHREADS;
        const int quad = idx & 7;
        kq[i] = quad * 4;
        if (idx < L_Q * 8) {               // A: queries
            const int row = idx >> 3;
            src[i] = qb + (size_t)row * E_DIM;
            inv[i] = s_invq[row];
            dst[i] = row * SW + quad * 4;
        } else {                            // B: docs
            const int row = (idx - L_Q * 8) >> 3;
            src[i] = db + (size_t)(n0g + row) * E_DIM;
            inv[i] = s_invd[row];
            dst[i] = BOFF_B + row * SW + quad * 4;
        }
    }

    float acc[2][4][4];
    #pragma unroll
    for (int mt = 0; mt < 2; ++mt)
        #pragma unroll
        for (int nt = 0; nt < 4; ++nt)
            #pragma unroll
            for (int c = 0; c < 4; ++c) acc[mt][nt][c] = 0.f;

    const int offA0 = (wm * 32 + qrow) * SW;          // + mt*16*SW, +8*SW for a1
    int offB[4];
    #pragma unroll
    for (int nt = 0; nt < 4; ++nt) offB[nt] = BOFF_B + (wn * 32 + nt * 8 + qrow) * SW;

    // prefetch chunk 0
    float4 pre[6];
    #pragma unroll
    for (int i = 0; i < 6; ++i) {
        const int k0 = kq[i];
        pre[i] = (k0 < E_DIM) ? *(const float4*)(src[i] + k0) : make_float4(0.f, 0.f, 0.f, 0.f);
    }

    for (int c = 0; c < NCK; ++c) {
        float* buf = smf + (c & 1) * BUF_W;
        // stage: normalize + tf32-round + STS.128
        #pragma unroll
        for (int i = 0; i < 6; ++i) {
            uint4 u;
            u.x = cvt_tf32(pre[i].x * inv[i]);
            u.y = cvt_tf32(pre[i].y * inv[i]);
            u.z = cvt_tf32(pre[i].z * inv[i]);
            u.w = cvt_tf32(pre[i].w * inv[i]);
            *(uint4*)(buf + dst[i]) = u;
        }
        __syncthreads();
        // prefetch next chunk (overlaps with MMA below)
        if (c + 1 < NCK) {
            const int kb = (c + 1) * KC;
            #pragma unroll
            for (int i = 0; i < 6; ++i) {
                const int k0 = kb + kq[i];
                pre[i] = (k0 < E_DIM) ? *(const float4*)(src[i] + k0)
                                      : make_float4(0.f, 0.f, 0.f, 0.f);
            }
        }
        // MMA: 4 k8-steps on this chunk
        const uint32_t* bw = (const uint32_t*)buf;
        #pragma unroll
        for (int s = 0; s < 4; ++s) {
            const int kc = s * 8 + c4;
            uint32_t a[2][4];
            #pragma unroll
            for (int mt = 0; mt < 2; ++mt) {
                const int oa = offA0 + mt * 16 * SW + kc;
                a[mt][0] = bw[oa];
                a[mt][1] = bw[oa + 8 * SW];
                a[mt][2] = bw[oa + 4];
                a[mt][3] = bw[oa + 8 * SW + 4];
            }
            uint32_t bf[4][2];
            #pragma unroll
            for (int nt = 0; nt < 4; ++nt) {
                bf[nt][0] = bw[offB[nt] + kc];
                bf[nt][1] = bw[offB[nt] + kc + 4];
            }
            #pragma unroll
            for (int mt = 0; mt < 2; ++mt)
                #pragma unroll
                for (int nt = 0; nt < 4; ++nt)
                    mma_tf32(acc[mt][nt], a[mt], bf[nt][0], bf[nt][1]);
        }
    }

    // ---- pooling straight from accumulator fragments ----
    #pragma unroll
    for (int mt = 0; mt < 2; ++mt) {
        #pragma unroll
        for (int rh = 0; rh < 2; ++rh) {
            const int row = wm * 32 + mt * 16 + qrow + rh * 8;   // query index
            float pl[N_K];
            #pragma unroll
            for (int k = 0; k < N_K; ++k) pl[k] = 0.f;
            #pragma unroll
            for (int nt = 0; nt < 4; ++nt) {
                #pragma unroll
                for (int cm = 0; cm < 2; ++cm) {
                    const int nl = wn * 32 + nt * 8 + c4 * 2 + cm;  // local doc
                    const float s  = acc[mt][nt][rh * 2 + cm];
                    const float mv = s_maskd[nl];
                    const float base = exp2ff(fmaxf(s * s * -72.134752f, -126.f)); // e^{-50 s^2}
                    const float t    = exp2ff(s * 14.4269504f);                    // e^{10 s}
                    const float r    = rcpa(t);
                    const float t2 = t * t, r2 = r * r;
                    const float A1 = (base * t) * 0.60653066f;
                    const float A3 = (A1 * t2) * 0.018315639f;
                    const float A5 = (A3 * t2) * 3.3546263e-4f;
                    const float A7 = (A5 * t2) * 6.1442124e-6f;
                    const float A9 = (A7 * t2) * 1.1253517e-7f;
                    const float B1 = (base * r) * 0.60653066f;
                    const float B3 = (B1 * r2) * 0.018315639f;
                    const float B5 = (B3 * r2) * 3.3546263e-4f;
                    const float B7 = (B5 * r2) * 6.1442124e-6f;
                    const float B9 = (B7 * r2) * 1.1253517e-7f;
                    pl[1]  = fmaf(mv, A9, pl[1]);
                    pl[2]  = fmaf(mv, A7, pl[2]);
                    pl[3]  = fmaf(mv, A5, pl[3]);
                    pl[4]  = fmaf(mv, A3, pl[4]);
                    pl[5]  = fmaf(mv, A1, pl[5]);
                    pl[6]  = fmaf(mv, B1, pl[6]);
                    pl[7]  = fmaf(mv, B3, pl[7]);
                    pl[8]  = fmaf(mv, B5, pl[8]);
                    pl[9]  = fmaf(mv, B7, pl[9]);
                    pl[10] = fmaf(mv, B9, pl[10]);
                    const float d1 = s - 1.0f;   // kernel 0: sigma=1e-3 (clipped in practice)
                    if (fabsf(d1) < 0.0125f) {
                        const float u = d1 * 849.321802f;
                        pl[0] = fmaf(mv, exp2ff(fmaxf(-u * u, -126.f)), pl[0]);
                    }
                }
            }
            #pragma unroll
            for (int k = 0; k < N_K; ++k) {
                float v = pl[k];
                v += __shfl_xor_sync(0xffffffffu, v, 1);
                v += __shfl_xor_sync(0xffffffffu, v, 2);
                if (c4 == 0) atomicAdd(&s_pool[row * N_K + k], v);
            }
        }
    }
    __syncthreads();

    // ---- publish chunk partials; last CTA of this batch finalizes ----
    float* gp = g_pool + (size_t)(b * NCHUNKS + chunk) * (L_Q * N_K);
    for (int i = tid; i < L_Q * N_K; i += NTHREADS) gp[i] = s_pool[i];
    __threadfence();
    __syncthreads();
    if (tid == 0) {
        unsigned int t = atomicAdd(&g_cnt[b], 1u);
        s_last = (t == NCHUNKS - 1);
    }
    __syncthreads();

    if (s_last) {
        __threadfence();
        const float* gb = g_pool + (size_t)b * NCHUNKS * L_Q * N_K;
        for (int i = tid; i < L_Q * N_K; i += NTHREADS)
            s_pool[i] = gb[i] + gb[L_Q * N_K + i] + gb[2 * L_Q * N_K + i] + gb[3 * L_Q * N_K + i];
        __syncthreads();
        if (tid < L_Q) {
            const float mqv = mq[b * L_Q + tid] * 0.01f;
            float cm = 0.f;
            #pragma unroll
            for (int k = 0; k < N_K; ++k)
                cm = fmaf(logf(fmaxf(s_pool[tid * N_K + k], 1e-10f)) * mqv, w[k], cm);
            s_red[tid] = cm;
        }
        __syncthreads();
        if (tid == 0) {
            float s = bias[0];
            #pragma unroll
            for (int m = 0; m < L_Q; ++m) s += s_red[m];
            out[b] = tanhf(s);
            g_cnt[b] = 0;   // reset for next graph replay
        }
    }
}

extern "C" void kernel_launch(void* const* d_in, const int* in_sizes, int n_in,
                              void* d_out, int out_size) {
    const float* q    = (const float*)d_in[0];   // [B, Lq, E]
    const float* d    = (const float*)d_in[1];   // [B, Ld, E]
    const float* mq   = (const float*)d_in[2];   // [B, Lq]
    const float* md   = (const float*)d_in[3];   // [B, Ld]
    const float* w    = (const float*)d_in[4];   // [1, K]
    const float* bias = (const float*)d_in[5];   // [1]
    float* out = (float*)d_out;                  // [B, 1]

    cudaFuncSetAttribute(knrm_tf32, cudaFuncAttributeMaxDynamicSharedMemorySize, SMEM_BYTES);
    dim3 grid(NCHUNKS, B_SZ);
    knrm_tf32<<<grid, NTHREADS, SMEM_BYTES>>>(q, d, mq, md, w, bias, out);
}

// round 8
// speedup vs baseline: 1.9567x; 1.5513x over previous
#include <cuda_runtime.h>
#include <math.h>
#include <stdint.h>

#define B_SZ     128
#define L_Q      64
#define L_D      512
#define E_DIM    300
#define N_K      11
#define NTG      128        // docs per group
#define NGRP     2          // doc groups per CTA
#define NPAIR    2          // grid.x (pairs of groups)
#define NTHREADS 256
#define KC       32         // k per pipeline chunk
#define NCK      10         // 10*32 = 320 >= 300 (zero-padded)
#define SW       36         // smem row stride (words) -> conflict-free

// smem word offsets
#define BUF_W     6912      // A 64*36 + B 128*36
#define BOFF_B    2304
#define OFF_MASKD (2 * BUF_W)          // 256
#define OFF_SS    (OFF_MASKD + 256)    // 192 sumsq
#define OFF_INV   (OFF_SS + 192)       // 192 inverse norms (q:0..63, d:64..191)
#define OFF_POOL  (OFF_INV + 192)      // 704
#define OFF_RED   (OFF_POOL + 704)     // 64
#define SMEM_WORDS (OFF_RED + 64)
#define SMEM_BYTES (SMEM_WORDS * 4)

__device__ float g_pool[B_SZ * NPAIR * L_Q * N_K];
__device__ unsigned int g_cnt[B_SZ];   // zero-init; last CTA resets (graph-replay safe)

__device__ __forceinline__ void mma_tf32(float* c, const uint32_t* a, uint32_t b0, uint32_t b1) {
    asm volatile("mma.sync.aligned.m16n8k8.row.col.f32.tf32.tf32.f32 "
        "{%0,%1,%2,%3},{%4,%5,%6,%7},{%8,%9},{%0,%1,%2,%3};"
        : "+f"(c[0]), "+f"(c[1]), "+f"(c[2]), "+f"(c[3])
        : "r"(a[0]), "r"(a[1]), "r"(a[2]), "r"(a[3]), "r"(b0), "r"(b1));
}
__device__ __forceinline__ uint32_t cvt_tf32(float x) {
    uint32_t r; asm("cvt.rna.tf32.f32 %0, %1;" : "=r"(r) : "f"(x)); return r;
}
__device__ __forceinline__ float rcpa(float x) {
    float r; asm("rcp.approx.f32 %0,%1;" : "=f"(r) : "f"(x)); return r;
}
// 2^y for y in [-126, 15], pure fma/alu, err ~2e-6
__device__ __forceinline__ float exp2ff(float y) {
    float z = __fadd_rn(y, 12582912.0f);
    float f = __fadd_rn(y, -__fadd_rn(z, -12582912.0f));
    float p =              1.3333558e-3f;
    p = fmaf(p, f, 9.6181293e-3f);
    p = fmaf(p, f, 5.5504109e-2f);
    p = fmaf(p, f, 2.4022650e-1f);
    p = fmaf(p, f, 6.9314718e-1f);
    p = fmaf(p, f, 1.0f);
    int n = __float_as_int(z) - 0x4B400000;
    return p * __int_as_float((n + 127) << 23);
}

__global__ __launch_bounds__(NTHREADS, 2)
void knrm_tf32(const float* __restrict__ q,
               const float* __restrict__ d,
               const float* __restrict__ mq,
               const float* __restrict__ md,
               const float* __restrict__ w,
               const float* __restrict__ bias,
               float* __restrict__ out)
{
    extern __shared__ float smf[];
    __shared__ int s_last;

    float* s_maskd = smf + OFF_MASKD;   // 256 docs (both groups)
    float* s_ss    = smf + OFF_SS;
    float* s_inv   = smf + OFF_INV;
    float* s_pool  = smf + OFF_POOL;
    float* s_red   = smf + OFF_RED;

    const int pair = blockIdx.x;        // 0..1
    const int b    = blockIdx.y;
    const int tid  = threadIdx.x;
    const int lane = tid & 31;
    const int warp = tid >> 5;
    const int wm   = warp >> 2;
    const int wn   = warp & 3;
    const int qrow = lane >> 2;
    const int c4   = lane & 3;

    const float* __restrict__ qb = q + (size_t)b * L_Q * E_DIM;
    const float* __restrict__ db = d + (size_t)b * L_D * E_DIM;

    for (int i = tid; i < NGRP * NTG; i += NTHREADS)
        s_maskd[i] = md[b * L_D + pair * NGRP * NTG + i];
    for (int i = tid; i < L_Q * N_K; i += NTHREADS) s_pool[i] = 0.f;

    // ---- per-thread staging slots (6 float4 / chunk), fixed (row, quad) ----
    const int sidx0 = tid;
    int dst[6], kq[6], ssrow[6];
    bool isA[6];
    int  arow[6];
    #pragma unroll
    for (int i = 0; i < 6; ++i) {
        const int idx = sidx0 + i * NTHREADS;
        const int quad = idx & 7;
        kq[i] = quad * 4;
        if (idx < L_Q * 8) {
            const int row = idx >> 3;
            isA[i] = true;  arow[i] = row;
            dst[i] = row * SW + quad * 4;
            ssrow[i] = row;
        } else {
            const int row = (idx - L_Q * 8) >> 3;
            isA[i] = false; arow[i] = row;
            dst[i] = BOFF_B + row * SW + quad * 4;
            ssrow[i] = 64 + row;
        }
    }

    const int offA0 = (wm * 32 + qrow) * SW;
    int offB[4];
    #pragma unroll
    for (int nt = 0; nt < 4; ++nt) offB[nt] = BOFF_B + (wn * 32 + nt * 8 + qrow) * SW;

    for (int g = 0; g < NGRP; ++g) {
        const int n0g = (pair * NGRP + g) * NTG;

        // group-local source pointers
        const float* src[6];
        #pragma unroll
        for (int i = 0; i < 6; ++i)
            src[i] = isA[i] ? (qb + (size_t)arow[i] * E_DIM)
                            : (db + (size_t)(n0g + arow[i]) * E_DIM);

        for (int i = tid; i < 192; i += NTHREADS) s_ss[i] = 0.f;

        float acc[2][4][4];
        #pragma unroll
        for (int mt = 0; mt < 2; ++mt)
            #pragma unroll
            for (int nt = 0; nt < 4; ++nt)
                #pragma unroll
                for (int c = 0; c < 4; ++c) acc[mt][nt][c] = 0.f;
        float ss[6];
        #pragma unroll
        for (int i = 0; i < 6; ++i) ss[i] = 0.f;

        // prefetch chunk 0
        float4 pre[6];
        #pragma unroll
        for (int i = 0; i < 6; ++i)
            pre[i] = (kq[i] < E_DIM) ? *(const float4*)(src[i] + kq[i])
                                     : make_float4(0.f, 0.f, 0.f, 0.f);

        for (int c = 0; c < NCK; ++c) {
            float* buf = smf + (c & 1) * BUF_W;
            // stage raw tf32 + accumulate sum-of-squares (raw fp32)
            #pragma unroll
            for (int i = 0; i < 6; ++i) {
                const float4 v = pre[i];
                ss[i] = fmaf(v.x, v.x, fmaf(v.y, v.y, fmaf(v.z, v.z, fmaf(v.w, v.w, ss[i]))));
                uint4 u;
                u.x = cvt_tf32(v.x); u.y = cvt_tf32(v.y);
                u.z = cvt_tf32(v.z); u.w = cvt_tf32(v.w);
                *(uint4*)(buf + dst[i]) = u;
            }
            __syncthreads();
            if (c + 1 < NCK) {
                const int kb = (c + 1) * KC;
                #pragma unroll
                for (int i = 0; i < 6; ++i) {
                    const int k0 = kb + kq[i];
                    pre[i] = (k0 < E_DIM) ? *(const float4*)(src[i] + k0)
                                          : make_float4(0.f, 0.f, 0.f, 0.f);
                }
            }
            const uint32_t* bw = (const uint32_t*)buf;
            #pragma unroll
            for (int s = 0; s < 4; ++s) {
                const int kc = s * 8 + c4;
                uint32_t a[2][4];
                #pragma unroll
                for (int mt = 0; mt < 2; ++mt) {
                    const int oa = offA0 + mt * 16 * SW + kc;
                    a[mt][0] = bw[oa];
                    a[mt][1] = bw[oa + 8 * SW];
                    a[mt][2] = bw[oa + 4];
                    a[mt][3] = bw[oa + 8 * SW + 4];
                }
                uint32_t bf[4][2];
                #pragma unroll
                for (int nt = 0; nt < 4; ++nt) {
                    bf[nt][0] = bw[offB[nt] + kc];
                    bf[nt][1] = bw[offB[nt] + kc + 4];
                }
                #pragma unroll
                for (int mt = 0; mt < 2; ++mt)
                    #pragma unroll
                    for (int nt = 0; nt < 4; ++nt)
                        mma_tf32(acc[mt][nt], a[mt], bf[nt][0], bf[nt][1]);
            }
        }

        // ---- norms: flush slot sumsq, compute inverse norms ----
        #pragma unroll
        for (int i = 0; i < 6; ++i) atomicAdd(&s_ss[ssrow[i]], ss[i]);
        __syncthreads();
        if (tid < 192) s_inv[tid] = 1.0f / fmaxf(sqrtf(s_ss[tid]), 1e-12f);
        __syncthreads();

        // ---- pooling from fragments, normalized at epilogue ----
        float ivd[8];
        float mvd[8];
        #pragma unroll
        for (int nt = 0; nt < 4; ++nt)
            #pragma unroll
            for (int cm = 0; cm < 2; ++cm) {
                const int nl = wn * 32 + nt * 8 + c4 * 2 + cm;
                ivd[nt * 2 + cm] = s_inv[64 + nl];
                mvd[nt * 2 + cm] = s_maskd[g * NTG + nl];
            }
        #pragma unroll
        for (int mt = 0; mt < 2; ++mt) {
            #pragma unroll
            for (int rh = 0; rh < 2; ++rh) {
                const int row = wm * 32 + mt * 16 + qrow + rh * 8;
                const float iq = s_inv[row];
                float pl[N_K];
                #pragma unroll
                for (int k = 0; k < N_K; ++k) pl[k] = 0.f;
                #pragma unroll
                for (int nt = 0; nt < 4; ++nt) {
                    #pragma unroll
                    for (int cm = 0; cm < 2; ++cm) {
                        const float s  = acc[mt][nt][rh * 2 + cm] * iq * ivd[nt * 2 + cm];
                        const float mv = mvd[nt * 2 + cm];
                        const float base = exp2ff(fmaxf(s * s * -72.134752f, -126.f));
                        const float t    = exp2ff(s * 14.4269504f);
                        const float r    = rcpa(t);
                        const float t2 = t * t, r2 = r * r;
                        const float A1 = (base * t) * 0.60653066f;
                        const float A3 = (A1 * t2) * 0.018315639f;
                        const float A5 = (A3 * t2) * 3.3546263e-4f;
                        const float A7 = (A5 * t2) * 6.1442124e-6f;
                        const float A9 = (A7 * t2) * 1.1253517e-7f;
                        const float B1 = (base * r) * 0.60653066f;
                        const float B3 = (B1 * r2) * 0.018315639f;
                        const float B5 = (B3 * r2) * 3.3546263e-4f;
                        const float B7 = (B5 * r2) * 6.1442124e-6f;
                        const float B9 = (B7 * r2) * 1.1253517e-7f;
                        pl[1]  = fmaf(mv, A9, pl[1]);
                        pl[2]  = fmaf(mv, A7, pl[2]);
                        pl[3]  = fmaf(mv, A5, pl[3]);
                        pl[4]  = fmaf(mv, A3, pl[4]);
                        pl[5]  = fmaf(mv, A1, pl[5]);
                        pl[6]  = fmaf(mv, B1, pl[6]);
                        pl[7]  = fmaf(mv, B3, pl[7]);
                        pl[8]  = fmaf(mv, B5, pl[8]);
                        pl[9]  = fmaf(mv, B7, pl[9]);
                        pl[10] = fmaf(mv, B9, pl[10]);
                        const float d1 = s - 1.0f;   // kernel 0: sigma=1e-3
                        if (fabsf(d1) < 0.0125f) {
                            const float u = d1 * 849.321802f;
                            pl[0] = fmaf(mv, exp2ff(fmaxf(-u * u, -126.f)), pl[0]);
                        }
                    }
                }
                #pragma unroll
                for (int k = 0; k < N_K; ++k) {
                    float v = pl[k];
                    v += __shfl_xor_sync(0xffffffffu, v, 1);
                    v += __shfl_xor_sync(0xffffffffu, v, 2);
                    if (c4 == 0) atomicAdd(&s_pool[row * N_K + k], v);
                }
            }
        }
        __syncthreads();   // pooling done before s_inv/s_ss reuse next group
    }

    // ---- publish pair partials; last CTA of this batch finalizes ----
    float* gp = g_pool + (size_t)(b * NPAIR + pair) * (L_Q * N_K);
    for (int i = tid; i < L_Q * N_K; i += NTHREADS) gp[i] = s_pool[i];
    __threadfence();
    __syncthreads();
    if (tid == 0) {
        unsigned int t = atomicAdd(&g_cnt[b], 1u);
        s_last = (t == NPAIR - 1);
    }
    __syncthreads();

    if (s_last) {
        __threadfence();
        const float* gb = g_pool + (size_t)b * NPAIR * L_Q * N_K;
        for (int i = tid; i < L_Q * N_K; i += NTHREADS)
            s_pool[i] = gb[i] + gb[L_Q * N_K + i];
        __syncthreads();
        if (tid < L_Q) {
            const float mqv = mq[b * L_Q + tid] * 0.01f;
            float cm = 0.f;
            #pragma unroll
            for (int k = 0; k < N_K; ++k)
                cm = fmaf(logf(fmaxf(s_pool[tid * N_K + k], 1e-10f)) * mqv, w[k], cm);
            s_red[tid] = cm;
        }
        __syncthreads();
        if (tid == 0) {
            float s = bias[0];
            #pragma unroll
            for (int m = 0; m < L_Q; ++m) s += s_red[m];
            out[b] = tanhf(s);
            g_cnt[b] = 0;   // reset for next graph replay
        }
    }
}

extern "C" void kernel_launch(void* const* d_in, const int* in_sizes, int n_in,
                              void* d_out, int out_size) {
    const float* q    = (const float*)d_in[0];   // [B, Lq, E]
    const float* d    = (const float*)d_in[1];   // [B, Ld, E]
    const float* mq   = (const float*)d_in[2];   // [B, Lq]
    const float* md   = (const float*)d_in[3];   // [B, Ld]
    const float* w    = (const float*)d_in[4];   // [1, K]
    const float* bias = (const float*)d_in[5];   // [1]
    float* out = (float*)d_out;                  // [B, 1]

    cudaFuncSetAttribute(knrm_tf32, cudaFuncAttributeMaxDynamicSharedMemorySize, SMEM_BYTES);
    dim3 grid(NPAIR, B_SZ);
    knrm_tf32<<<grid, NTHREADS, SMEM_BYTES>>>(q, d, mq, md, w, bias, out);
}

// round 9
// speedup vs baseline: 2.0919x; 1.0691x over previous
#include <cuda_runtime.h>
#include <math.h>
#include <stdint.h>

#define B_SZ     128
#define L_Q      64
#define L_D      512
#define E_DIM    300
#define N_K      11
#define NTG      128        // docs per group
#define NGRP     2          // doc groups per CTA
#define NPAIR    2          // grid.x
#define NTHREADS 256
#define KC       32         // k per pipeline chunk
#define GC       10         // chunks per group (10*32 = 320 >= 300)
#define NCC      20         // total chunks per CTA
#define SW       36         // smem row stride (words) -> conflict-free

// smem word offsets
#define BUF_W     6912      // A 64*36 + B 128*36
#define BOFF_B    2304
#define OFF_MASKD (2 * BUF_W)          // 256
#define OFF_SS    (OFF_MASKD + 256)    // 192 sumsq
#define OFF_INV   (OFF_SS + 192)       // 192 inverse norms (q:0..63, d:64..191)
#define OFF_POOL  (OFF_INV + 192)      // 704
#define OFF_RED   (OFF_POOL + 704)     // 64
#define SMEM_WORDS (OFF_RED + 64)
#define SMEM_BYTES (SMEM_WORDS * 4)

__device__ float g_pool[B_SZ * NPAIR * L_Q * N_K];
__device__ unsigned int g_cnt[B_SZ];   // zero-init; last CTA resets (graph-replay safe)

__device__ __forceinline__ uint32_t smem_u32(const void* p) {
    uint32_t a;
    asm("{ .reg .u64 t; cvta.to.shared.u64 t, %1; cvt.u32.u64 %0, t; }" : "=r"(a) : "l"(p));
    return a;
}
__device__ __forceinline__ void mma_tf32(float* c, const uint32_t* a, uint32_t b0, uint32_t b1) {
    asm volatile("mma.sync.aligned.m16n8k8.row.col.f32.tf32.tf32.f32 "
        "{%0,%1,%2,%3},{%4,%5,%6,%7},{%8,%9},{%0,%1,%2,%3};"
        : "+f"(c[0]), "+f"(c[1]), "+f"(c[2]), "+f"(c[3])
        : "r"(a[0]), "r"(a[1]), "r"(a[2]), "r"(a[3]), "r"(b0), "r"(b1));
}
__device__ __forceinline__ void cp16(uint32_t dst, const void* src, int sz) {
    asm volatile("cp.async.cg.shared.global [%0], [%1], 16, %2;"
        :: "r"(dst), "l"(src), "r"(sz) : "memory");
}
#define CP_COMMIT() asm volatile("cp.async.commit_group;" ::: "memory")
#define CP_WAIT0()  asm volatile("cp.async.wait_group 0;" ::: "memory")

__device__ __forceinline__ float rcpa(float x) {
    float r; asm("rcp.approx.f32 %0,%1;" : "=f"(r) : "f"(x)); return r;
}
// 2^y for y in [-126, 15], pure fma/alu, err ~2e-6
__device__ __forceinline__ float exp2ff(float y) {
    float z = __fadd_rn(y, 12582912.0f);
    float f = __fadd_rn(y, -__fadd_rn(z, -12582912.0f));
    float p =              1.3333558e-3f;
    p = fmaf(p, f, 9.6181293e-3f);
    p = fmaf(p, f, 5.5504109e-2f);
    p = fmaf(p, f, 2.4022650e-1f);
    p = fmaf(p, f, 6.9314718e-1f);
    p = fmaf(p, f, 1.0f);
    int n = __float_as_int(z) - 0x4B400000;
    return p * __int_as_float((n + 127) << 23);
}

__global__ __launch_bounds__(NTHREADS, 2)
void knrm_tf32(const float* __restrict__ q,
               const float* __restrict__ d,
               const float* __restrict__ mq,
               const float* __restrict__ md,
               const float* __restrict__ w,
               const float* __restrict__ bias,
               float* __restrict__ out)
{
    extern __shared__ float smf[];
    __shared__ int s_last;

    float* s_maskd = smf + OFF_MASKD;   // 256 docs (both groups)
    float* s_ss    = smf + OFF_SS;
    float* s_inv   = smf + OFF_INV;
    float* s_pool  = smf + OFF_POOL;
    float* s_red   = smf + OFF_RED;

    const uint32_t smb = smem_u32(smf);
    const int pair = blockIdx.x;        // 0..1
    const int b    = blockIdx.y;
    const int tid  = threadIdx.x;
    const int lane = tid & 31;
    const int warp = tid >> 5;
    const int wm   = warp >> 2;
    const int wn   = warp & 3;
    const int qrow = lane >> 2;
    const int c4   = lane & 3;

    const float* __restrict__ qb = q + (size_t)b * L_Q * E_DIM;
    const float* __restrict__ db = d + (size_t)b * L_D * E_DIM;

    for (int i = tid; i < NGRP * NTG; i += NTHREADS)
        s_maskd[i] = md[b * L_D + pair * NGRP * NTG + i];
    for (int i = tid; i < L_Q * N_K; i += NTHREADS) s_pool[i] = 0.f;
    __syncthreads();

    // ---- per-thread staging slots (6 x 16B / chunk), fixed (row, quad) ----
    const float* sbase[6];   // includes +quad*4 element offset
    uint32_t dstw[6];        // smem byte addr (buffer 0)
    int      kqo[6];         // quad*4
    bool     slotA[6];
    #pragma unroll
    for (int i = 0; i < 6; ++i) {
        const int idx = tid + i * NTHREADS;
        const int quad = idx & 7;
        const int row  = idx >> 3;
        kqo[i] = quad * 4;
        if (row < L_Q) {
            slotA[i] = true;
            sbase[i] = qb + (size_t)row * E_DIM + kqo[i];
            dstw[i]  = smb + (row * SW + quad * 4) * 4;
        } else {
            slotA[i] = false;
            const int dr = row - L_Q;
            sbase[i] = db + (size_t)(pair * NGRP * NTG + dr) * E_DIM + kqo[i];
            dstw[i]  = smb + (BOFF_B + dr * SW + quad * 4) * 4;
        }
    }

    const int offA0 = (wm * 32 + qrow) * SW;
    int offB[4];
    #pragma unroll
    for (int nt = 0; nt < 4; ++nt) offB[nt] = BOFF_B + (wn * 32 + nt * 8 + qrow) * SW;

    float acc[2][4][4];
    #pragma unroll
    for (int mt = 0; mt < 2; ++mt)
        #pragma unroll
        for (int nt = 0; nt < 4; ++nt)
            #pragma unroll
            for (int c = 0; c < 4; ++c) acc[mt][nt][c] = 0.f;
    float ssA[4], ssB[4];
    #pragma unroll
    for (int i = 0; i < 4; ++i) { ssA[i] = 0.f; ssB[i] = 0.f; }

    // issue chunk 0
    #pragma unroll
    for (int i = 0; i < 6; ++i) {
        const int sz = (kqo[i] < E_DIM) ? 16 : 0;
        cp16(dstw[i], sbase[i], sz);
    }
    CP_COMMIT();

    #pragma unroll 1
    for (int cc = 0; cc < NCC; ++cc) {
        CP_WAIT0();            // chunk cc resident
        __syncthreads();       // visible to all; prior readers of other buffer done
        if (cc + 1 < NCC) {    // issue chunk cc+1 into the other buffer
            const int kb   = ((cc + 1) % GC) * KC;
            const int goff = (cc + 1 >= GC) ? NTG * E_DIM : 0;
            const uint32_t bsel = ((cc + 1) & 1) * (BUF_W * 4);
            #pragma unroll
            for (int i = 0; i < 6; ++i) {
                const bool ok = (kb + kqo[i]) < E_DIM;
                const float* p = sbase[i] + kb + (slotA[i] ? 0 : goff);
                cp16(dstw[i] + bsel, ok ? p : sbase[i], ok ? 16 : 0);
            }
            CP_COMMIT();
        }
        // ---- MMA on chunk cc (raw fp32; mma.tf32 truncates in HW) ----
        const uint32_t* bw = (const uint32_t*)(smf + (cc & 1) * BUF_W);
        #pragma unroll
        for (int s = 0; s < 4; ++s) {
            const int kc = s * 8 + c4;
            uint32_t a[2][4];
            #pragma unroll
            for (int mt = 0; mt < 2; ++mt) {
                const int oa = offA0 + mt * 16 * SW + kc;
                a[mt][0] = bw[oa];
                a[mt][1] = bw[oa + 8 * SW];
                a[mt][2] = bw[oa + 4];
                a[mt][3] = bw[oa + 8 * SW + 4];
            }
            uint32_t bf[4][2];
            #pragma unroll
            for (int nt = 0; nt < 4; ++nt) {
                bf[nt][0] = bw[offB[nt] + kc];
                bf[nt][1] = bw[offB[nt] + kc + 4];
            }
            // norm side-accumulation (owner warps only; warp-uniform predicate)
            if (wn == 0) {
                #pragma unroll
                for (int mt = 0; mt < 2; ++mt) {
                    float a0 = __uint_as_float(a[mt][0]), a2 = __uint_as_float(a[mt][2]);
                    float a1 = __uint_as_float(a[mt][1]), a3 = __uint_as_float(a[mt][3]);
                    ssA[mt * 2 + 0] = fmaf(a0, a0, fmaf(a2, a2, ssA[mt * 2 + 0]));
                    ssA[mt * 2 + 1] = fmaf(a1, a1, fmaf(a3, a3, ssA[mt * 2 + 1]));
                }
            }
            if (wm == 0) {
                #pragma unroll
                for (int nt = 0; nt < 4; ++nt) {
                    float b0 = __uint_as_float(bf[nt][0]), b1 = __uint_as_float(bf[nt][1]);
                    ssB[nt] = fmaf(b0, b0, fmaf(b1, b1, ssB[nt]));
                }
            }
            #pragma unroll
            for (int mt = 0; mt < 2; ++mt)
                #pragma unroll
                for (int nt = 0; nt < 4; ++nt)
                    mma_tf32(acc[mt][nt], a[mt], bf[nt][0], bf[nt][1]);
        }

        // ---- group epilogue: norms + pooling ----
        if ((cc % GC) == (GC - 1)) {
            const int g = cc / GC;
            #pragma unroll
            for (int i = 0; i < 4; ++i) {
                ssA[i] += __shfl_xor_sync(0xffffffffu, ssA[i], 1);
                ssA[i] += __shfl_xor_sync(0xffffffffu, ssA[i], 2);
                ssB[i] += __shfl_xor_sync(0xffffffffu, ssB[i], 1);
                ssB[i] += __shfl_xor_sync(0xffffffffu, ssB[i], 2);
            }
            if (c4 == 0) {
                if (wn == 0) {
                    #pragma unroll
                    for (int mt = 0; mt < 2; ++mt)
                        #pragma unroll
                        for (int rh = 0; rh < 2; ++rh)
                            s_ss[wm * 32 + mt * 16 + rh * 8 + qrow] = ssA[mt * 2 + rh];
                }
                if (wm == 0) {
                    #pragma unroll
                    for (int nt = 0; nt < 4; ++nt)
                        s_ss[64 + wn * 32 + nt * 8 + qrow] = ssB[nt];
                }
            }
            __syncthreads();
            if (tid < 192) s_inv[tid] = 1.0f / fmaxf(sqrtf(s_ss[tid]), 1e-12f);
            __syncthreads();

            float ivd[8], mvd[8];
            #pragma unroll
            for (int nt = 0; nt < 4; ++nt)
                #pragma unroll
                for (int cm = 0; cm < 2; ++cm) {
                    const int nl = wn * 32 + nt * 8 + c4 * 2 + cm;
                    ivd[nt * 2 + cm] = s_inv[64 + nl];
                    mvd[nt * 2 + cm] = s_maskd[g * NTG + nl];
                }
            #pragma unroll
            for (int mt = 0; mt < 2; ++mt) {
                #pragma unroll
                for (int rh = 0; rh < 2; ++rh) {
                    const int row = wm * 32 + mt * 16 + qrow + rh * 8;
                    const float iq = s_inv[row];
                    float pl[N_K];
                    #pragma unroll
                    for (int k = 0; k < N_K; ++k) pl[k] = 0.f;
                    #pragma unroll
                    for (int nt = 0; nt < 4; ++nt) {
                        #pragma unroll
                        for (int cm = 0; cm < 2; ++cm) {
                            const float s  = acc[mt][nt][rh * 2 + cm] * iq * ivd[nt * 2 + cm];
                            const float mv = mvd[nt * 2 + cm];
                            const float base = exp2ff(fmaxf(s * s * -72.134752f, -126.f));
                            const float t    = exp2ff(s * 14.4269504f);
                            const float r    = rcpa(t);
                            const float t2 = t * t, r2 = r * r;
                            const float A1 = (base * t) * 0.60653066f;
                            const float A3 = (A1 * t2) * 0.018315639f;
                            const float A5 = (A3 * t2) * 3.3546263e-4f;
                            const float A7 = (A5 * t2) * 6.1442124e-6f;
                            const float A9 = (A7 * t2) * 1.1253517e-7f;
                            const float B1 = (base * r) * 0.60653066f;
                            const float B3 = (B1 * r2) * 0.018315639f;
                            const float B5 = (B3 * r2) * 3.3546263e-4f;
                            const float B7 = (B5 * r2) * 6.1442124e-6f;
                            const float B9 = (B7 * r2) * 1.1253517e-7f;
                            pl[1]  = fmaf(mv, A9, pl[1]);
                            pl[2]  = fmaf(mv, A7, pl[2]);
                            pl[3]  = fmaf(mv, A5, pl[3]);
                            pl[4]  = fmaf(mv, A3, pl[4]);
                            pl[5]  = fmaf(mv, A1, pl[5]);
                            pl[6]  = fmaf(mv, B1, pl[6]);
                            pl[7]  = fmaf(mv, B3, pl[7]);
                            pl[8]  = fmaf(mv, B5, pl[8]);
                            pl[9]  = fmaf(mv, B7, pl[9]);
                            pl[10] = fmaf(mv, B9, pl[10]);
                            const float d1 = s - 1.0f;   // kernel 0: sigma=1e-3
                            if (fabsf(d1) < 0.0125f) {
                                const float u = d1 * 849.321802f;
                                pl[0] = fmaf(mv, exp2ff(fmaxf(-u * u, -126.f)), pl[0]);
                            }
                        }
                    }
                    #pragma unroll
                    for (int k = 0; k < N_K; ++k) {
                        float v = pl[k];
                        v += __shfl_xor_sync(0xffffffffu, v, 1);
                        v += __shfl_xor_sync(0xffffffffu, v, 2);
                        if (c4 == 0) atomicAdd(&s_pool[row * N_K + k], v);
                    }
                }
            }
            // reset accumulators for next group
            #pragma unroll
            for (int mt = 0; mt < 2; ++mt)
                #pragma unroll
                for (int nt = 0; nt < 4; ++nt)
                    #pragma unroll
                    for (int c = 0; c < 4; ++c) acc[mt][nt][c] = 0.f;
            #pragma unroll
            for (int i = 0; i < 4; ++i) { ssA[i] = 0.f; ssB[i] = 0.f; }
            __syncthreads();
        }
    }

    // ---- publish pair partials; last CTA of this batch finalizes ----
    float* gp = g_pool + (size_t)(b * NPAIR + pair) * (L_Q * N_K);
    for (int i = tid; i < L_Q * N_K; i += NTHREADS) gp[i] = s_pool[i];
    __threadfence();
    __syncthreads();
    if (tid == 0) {
        unsigned int t = atomicAdd(&g_cnt[b], 1u);
        s_last = (t == NPAIR - 1);
    }
    __syncthreads();

    if (s_last) {
        __threadfence();
        const float* gb = g_pool + (size_t)b * NPAIR * L_Q * N_K;
        for (int i = tid; i < L_Q * N_K; i += NTHREADS)
            s_pool[i] = gb[i] + gb[L_Q * N_K + i];
        __syncthreads();
        if (tid < L_Q) {
            const float mqv = mq[b * L_Q + tid] * 0.01f;
            float cm = 0.f;
            #pragma unroll
            for (int k = 0; k < N_K; ++k)
                cm = fmaf(logf(fmaxf(s_pool[tid * N_K + k], 1e-10f)) * mqv, w[k], cm);
            s_red[tid] = cm;
        }
        __syncthreads();
        if (tid == 0) {
            float s = bias[0];
            #pragma unroll
            for (int m = 0; m < L_Q; ++m) s += s_red[m];
            out[b] = tanhf(s);
            g_cnt[b] = 0;   // reset for next graph replay
        }
    }
}

extern "C" void kernel_launch(void* const* d_in, const int* in_sizes, int n_in,
                              void* d_out, int out_size) {
    const float* q    = (const float*)d_in[0];   // [B, Lq, E]
    const float* d    = (const float*)d_in[1];   // [B, Ld, E]
    const float* mq   = (const float*)d_in[2];   // [B, Lq]
    const float* md   = (const float*)d_in[3];   // [B, Ld]
    const float* w    = (const float*)d_in[4];   // [1, K]
    const float* bias = (const float*)d_in[5];   // [1]
    float* out = (float*)d_out;                  // [B, 1]

    cudaFuncSetAttribute(knrm_tf32, cudaFuncAttributeMaxDynamicSharedMemorySize, SMEM_BYTES);
    dim3 grid(NPAIR, B_SZ);
    knrm_tf32<<<grid, NTHREADS, SMEM_BYTES>>>(q, d, mq, md, w, bias, out);
}